// round 10
// baseline (speedup 1.0000x reference)
#include <cuda_runtime.h>
#include <math.h>

#define N_NODES 50000
#define N_EDGES 800000
#define N_GRAPHS 500
#define C 64
#define FE 16
#define NL 13
#define EPSBN 1e-5f
#define NCHUNK 49   // ceil(50000/1024)

typedef unsigned long long ull;

static __device__ __forceinline__ ull d_pack2(float lo, float hi) {
    ull r; asm("mov.b64 %0,{%1,%2};" : "=l"(r) : "f"(lo), "f"(hi)); return r;
}
static __device__ __forceinline__ void d_unpack2(ull v, float& lo, float& hi) {
    asm("mov.b64 {%0,%1},%2;" : "=f"(lo), "=f"(hi) : "l"(v));
}
static __device__ __forceinline__ ull d_fma2(ull a, ull b, ull c) {
    ull d; asm("fma.rn.f32x2 %0,%1,%2,%3;" : "=l"(d) : "l"(a), "l"(b), "l"(c)); return d;
}

// ---------------- scratch ----------------
__device__ float g_h[N_NODES * C];
__device__ float g_cur[N_NODES * C];
__device__ float g_S[N_NODES * C];
__device__ float g_coef[(size_t)NL * N_EDGES];   // raw sigmoid edge weights, CSR order
__device__ float g_dis[NL * N_NODES];
__device__ int   g_off[N_NODES + 1];
__device__ int   g_cnt[N_NODES];
__device__ int   g_csr_src[N_EDGES];
__device__ int   g_csr_eid[N_EDGES];             // CSR slot -> original edge id
__device__ float g_bn[256];                      // two ping-pong stat buffers of 128
__device__ float g_pool[N_GRAPHS * C];
__device__ int   g_chunk[64];
__device__ int   g_choff[64];

// ---------------- CSR build ----------------
__global__ void k_hist(const int* __restrict__ dst) {
    int e = blockIdx.x * blockDim.x + threadIdx.x;
    if (e < N_EDGES) atomicAdd(&g_cnt[dst[e]], 1);
}

__global__ void k_scan1() {
    __shared__ int sh[1024];
    int b = blockIdx.x, t = threadIdx.x;
    int i = b * 1024 + t;
    int v = (i < N_NODES) ? g_cnt[i] : 0;
    if (i < N_NODES) g_cnt[i] = 0;   // reset scatter cursor
    sh[t] = v;
    __syncthreads();
    for (int d = 1; d < 1024; d <<= 1) {
        int x = (t >= d) ? sh[t - d] : 0;
        __syncthreads();
        sh[t] += x;
        __syncthreads();
    }
    if (i < N_NODES) g_off[i] = sh[t] - v;  // local exclusive
    if (t == 1023) g_chunk[b] = sh[1023];
}

__global__ void k_scan2() {
    __shared__ int sh[64];
    int t = threadIdx.x;
    int v = (t < NCHUNK) ? g_chunk[t] : 0;
    sh[t] = v;
    __syncthreads();
    for (int d = 1; d < 64; d <<= 1) {
        int x = (t >= d) ? sh[t - d] : 0;
        __syncthreads();
        sh[t] += x;
        __syncthreads();
    }
    if (t < NCHUNK) g_choff[t] = sh[t] - v;
    if (t == 63) g_off[N_NODES] = sh[63];
}

__global__ void k_scan3() {
    int i = blockIdx.x * blockDim.x + threadIdx.x;
    if (i < N_NODES) g_off[i] += g_choff[i >> 10];
}

__global__ void k_scatter(const int* __restrict__ src, const int* __restrict__ dst) {
    int e = blockIdx.x * blockDim.x + threadIdx.x;
    if (e >= N_EDGES) return;
    int d = dst[e];
    int pos = atomicAdd(&g_cnt[d], 1);
    int s = g_off[d] + pos;
    g_csr_src[s] = src[e];
    g_csr_eid[s] = e;
}

// ---------------- edge MLP: per CSR slot, 4 slots/thread, f32x2 packed ----------------
// Gathers attr rows (random 64B reads), writes all 13 layers' coefs COALESCED.
#define EPT 4
__global__ __launch_bounds__(256) void k_edge_mlp(
    const float* __restrict__ attr,
    const float* __restrict__ m1W1, const float* __restrict__ m1b1,
    const float* __restrict__ m2W1, const float* __restrict__ m2b1,
    const float* __restrict__ hm1W, const float* __restrict__ hm1b,
    const float* __restrict__ hm2W, const float* __restrict__ hm2b)
{
    __shared__ ull   sW[NL][FE][FE];   // dup-packed W1^T: [l][j][k] = (w,w)
    __shared__ ull   sb1d[NL][FE];     // dup-packed bias1
    __shared__ float sw2[NL][FE];
    __shared__ float sb2v[NL];
    int t = threadIdx.x;
    for (int i = t; i < NL * FE * FE; i += 256) {
        int l = i / (FE * FE), r = i % (FE * FE);
        int k = r / FE, j = r % FE;
        float w = (l == 0) ? m1W1[k * FE + j] : hm1W[(l - 1) * FE * FE + k * FE + j];
        sW[l][j][k] = d_pack2(w, w);
    }
    for (int i = t; i < NL * FE; i += 256) {
        int l = i / FE, j = i % FE;
        float b = (l == 0) ? m1b1[j] : hm1b[(l - 1) * FE + j];
        sb1d[l][j] = d_pack2(b, b);
        sw2[l][j] = (l == 0) ? m2W1[j] : hm2W[(l - 1) * FE + j];
    }
    if (t < NL) sb2v[t] = (t == 0) ? m2b1[0] : hm2b[t - 1];
    __syncthreads();

    int base = blockIdx.x * (256 * EPT) + t;
    bool val[EPT];
    int sl[EPT];
    float a[EPT][16];
    #pragma unroll
    for (int j = 0; j < EPT; j++) {
        int s = base + j * 256;
        val[j] = (s < N_EDGES);
        sl[j] = val[j] ? s : 0;
        int eid = val[j] ? g_csr_eid[s] : 0;
        const float4* ap = (const float4*)(attr + (size_t)eid * 16);
        float4 a0 = ap[0], a1 = ap[1], a2 = ap[2], a3 = ap[3];
        a[j][0]=a0.x; a[j][1]=a0.y; a[j][2]=a0.z; a[j][3]=a0.w;
        a[j][4]=a1.x; a[j][5]=a1.y; a[j][6]=a1.z; a[j][7]=a1.w;
        a[j][8]=a2.x; a[j][9]=a2.y; a[j][10]=a2.z; a[j][11]=a2.w;
        a[j][12]=a3.x; a[j][13]=a3.y; a[j][14]=a3.z; a[j][15]=a3.w;
    }
    ull ap0[16], ap1[16];
    #pragma unroll
    for (int k = 0; k < 16; k++) {
        ap0[k] = d_pack2(a[0][k], a[1][k]);
        ap1[k] = d_pack2(a[2][k], a[3][k]);
    }

    #pragma unroll 1
    for (int l = 0; l < NL; l++) {
        float out0 = 0.f, out1 = 0.f, out2 = 0.f, out3 = 0.f;
        #pragma unroll
        for (int jj = 0; jj < FE; jj++) {
            ull acc0 = sb1d[l][jj], acc1 = acc0;
            const ulonglong2* wp = (const ulonglong2*)&sW[l][jj][0];
            #pragma unroll
            for (int kk = 0; kk < 8; kk++) {
                ulonglong2 wv = wp[kk];
                acc0 = d_fma2(ap0[2 * kk],     wv.x, acc0);
                acc0 = d_fma2(ap0[2 * kk + 1], wv.y, acc0);
                acc1 = d_fma2(ap1[2 * kk],     wv.x, acc1);
                acc1 = d_fma2(ap1[2 * kk + 1], wv.y, acc1);
            }
            float h0, h1, h2, h3;
            d_unpack2(acc0, h0, h1);
            d_unpack2(acc1, h2, h3);
            float w2s = sw2[l][jj];
            out0 += fmaxf(h0, 0.f) * w2s;
            out1 += fmaxf(h1, 0.f) * w2s;
            out2 += fmaxf(h2, 0.f) * w2s;
            out3 += fmaxf(h3, 0.f) * w2s;
        }
        float b2 = sb2v[l];
        float o[EPT] = {out0 + b2, out1 + b2, out2 + b2, out3 + b2};
        float* cf = g_coef + (size_t)l * N_EDGES;
        #pragma unroll
        for (int j = 0; j < EPT; j++)
            if (val[j]) cf[sl[j]] = 1.f / (1.f + __expf(-o[j]));   // coalesced (stride 256)
    }
}

// ---------------- dis = rsqrt(1 + sum ew) ; also zero pool ----------------
__global__ void k_dis() {
    int i = blockIdx.x * blockDim.x + threadIdx.x;
    if (i < N_GRAPHS * C) g_pool[i] = 0.f;
    if (i >= NL * N_NODES) return;
    int l = i / N_NODES, n = i % N_NODES;
    int b = g_off[n], e2 = g_off[n + 1];
    const float* cw = g_coef + (size_t)l * N_EDGES;
    float d0 = 1.f, d1 = 0.f, d2 = 0.f, d3 = 0.f;
    int s = b;
    for (; s + 3 < e2; s += 4) { d0 += cw[s]; d1 += cw[s+1]; d2 += cw[s+2]; d3 += cw[s+3]; }
    for (; s < e2; s++) d0 += cw[s];
    g_dis[i] = rsqrtf(d0 + d1 + d2 + d3);
}

// ---------------- GEMM: g_h = f(X) @ W  (f32x2 packed) ----------------
template <int BN>
__global__ __launch_bounds__(256) void k_gemm(const float* __restrict__ X,
                                              const float* __restrict__ W,
                                              int rbuf, int zbuf)
{
    __shared__ ull   sxd[64][64];   // dup-packed activations [row][k]
    __shared__ float sw[64][64];    // W [k][col]
    int t = threadIdx.x;

    for (int i = t; i < 1024; i += 256) {
        float4 v = ((const float4*)W)[i];
        int k = i >> 4, c4 = (i & 15) << 2;
        sw[k][c4] = v.x; sw[k][c4 + 1] = v.y; sw[k][c4 + 2] = v.z; sw[k][c4 + 3] = v.w;
    }

    float mu[4], rs[4];
    if (BN) {
        const float* sb = g_bn + rbuf;
        int k0 = (t & 15) << 2;
        #pragma unroll
        for (int u = 0; u < 4; u++) {
            float s = sb[k0 + u], q = sb[64 + k0 + u];
            float m = s * (1.f / N_NODES);
            float var = q * (1.f / N_NODES) - m * m;
            mu[u] = m; rs[u] = rsqrtf(var + EPSBN);
        }
    }

    int row0 = blockIdx.x * 64;
    const float* Xp = BN ? g_cur : X;
    for (int i = t; i < 1024; i += 256) {
        int r = i >> 4, c4g = i & 15;
        int n = row0 + r;
        float4 v = make_float4(0.f, 0.f, 0.f, 0.f);
        if (n < N_NODES) v = ((const float4*)(Xp + (size_t)n * 64))[c4g];
        if (BN) {
            v.x = fmaxf((v.x - mu[0]) * rs[0], 0.f);
            v.y = fmaxf((v.y - mu[1]) * rs[1], 0.f);
            v.z = fmaxf((v.z - mu[2]) * rs[2], 0.f);
            v.w = fmaxf((v.w - mu[3]) * rs[3], 0.f);
        }
        int kb = c4g << 2;
        sxd[r][kb]     = d_pack2(v.x, v.x);
        sxd[r][kb + 1] = d_pack2(v.y, v.y);
        sxd[r][kb + 2] = d_pack2(v.z, v.z);
        sxd[r][kb + 3] = d_pack2(v.w, v.w);
    }
    if (blockIdx.x == 0 && t < 128) g_bn[zbuf + t] = 0.f;  // zero stats buf for this layer's agg
    __syncthreads();

    int c2 = t & 15, rg = t >> 4;
    ull acc[4][2];
    #pragma unroll
    for (int i2 = 0; i2 < 4; i2++) { acc[i2][0] = 0ull; acc[i2][1] = 0ull; }

    #pragma unroll 16
    for (int k = 0; k < 64; k++) {
        ulonglong2 b2 = *(const ulonglong2*)&sw[k][c2 << 2];
        #pragma unroll
        for (int i2 = 0; i2 < 4; i2++) {
            ull av = sxd[(rg << 2) + i2][k];
            acc[i2][0] = d_fma2(av, b2.x, acc[i2][0]);
            acc[i2][1] = d_fma2(av, b2.y, acc[i2][1]);
        }
    }
    #pragma unroll
    for (int i2 = 0; i2 < 4; i2++) {
        int n = row0 + (rg << 2) + i2;
        if (n < N_NODES) {
            float x0, x1, x2, x3;
            d_unpack2(acc[i2][0], x0, x1);
            d_unpack2(acc[i2][1], x2, x3);
            ((float4*)(g_h + (size_t)n * 64))[c2] = make_float4(x0, x1, x2, x3);
        }
    }
}

// ---------------- aggregation + fused epilogues ----------------
// MODE bits: 1=init S, 2=add skip, 4=BN stats, 8=relu+pool (final)
template <int MODE>
__global__ __launch_bounds__(256) void k_agg(int l, const float* __restrict__ bias,
                                             const int* __restrict__ batch)
{
    __shared__ float s_red[128];
    if (MODE & 4) {
        if (threadIdx.x < 128) s_red[threadIdx.x] = 0.f;
        __syncthreads();
    }
    int n = (blockIdx.x * 256 + threadIdx.x) >> 5;
    int lane = threadIdx.x & 31;
    int b = g_off[n], e2 = g_off[n + 1];
    const float* __restrict__ cf = g_coef + (size_t)l * N_EDGES;
    const float* __restrict__ disl = g_dis + l * N_NODES;
    float2 acc = make_float2(0.f, 0.f);
    int s = b;
    for (; s + 3 < e2; s += 4) {
        int i0 = g_csr_src[s], i1 = g_csr_src[s + 1], i2 = g_csr_src[s + 2], i3 = g_csr_src[s + 3];
        float w0 = cf[s] * disl[i0], w1 = cf[s + 1] * disl[i1];
        float w2 = cf[s + 2] * disl[i2], w3 = cf[s + 3] * disl[i3];
        float2 h0 = ((const float2*)(g_h + (size_t)i0 * 64))[lane];
        float2 h1 = ((const float2*)(g_h + (size_t)i1 * 64))[lane];
        float2 h2 = ((const float2*)(g_h + (size_t)i2 * 64))[lane];
        float2 h3 = ((const float2*)(g_h + (size_t)i3 * 64))[lane];
        acc.x += w0 * h0.x + w1 * h1.x + w2 * h2.x + w3 * h3.x;
        acc.y += w0 * h0.y + w1 * h1.y + w2 * h2.y + w3 * h3.y;
    }
    for (; s < e2; s++) {
        int i0 = g_csr_src[s];
        float w0 = cf[s] * disl[i0];
        float2 h0 = ((const float2*)(g_h + (size_t)i0 * 64))[lane];
        acc.x += w0 * h0.x;
        acc.y += w0 * h0.y;
    }
    float dn = disl[n];
    float2 hs = ((const float2*)(g_h + (size_t)n * 64))[lane];
    float2 bb = ((const float2*)bias)[lane];
    float2 c;
    c.x = dn * acc.x + dn * dn * hs.x + bb.x;
    c.y = dn * acc.y + dn * dn * hs.y + bb.y;

    if (MODE & 2) {
        float2 Sv = ((const float2*)(g_S + (size_t)n * 64))[lane];
        c.x += Sv.x; c.y += Sv.y;
        if (!(MODE & 8))
            ((float2*)(g_S + (size_t)n * 64))[lane] = make_float2(Sv.x + c.x, Sv.y + c.y);
    }
    if (MODE & 1)
        ((float2*)(g_S + (size_t)n * 64))[lane] = c;
    if (!(MODE & 8))
        ((float2*)(g_cur + (size_t)n * 64))[lane] = c;
    if (MODE & 8) {
        int g = batch[n];
        atomicMax((unsigned int*)&g_pool[g * 64 + 2 * lane],     __float_as_uint(fmaxf(c.x, 0.f)));
        atomicMax((unsigned int*)&g_pool[g * 64 + 2 * lane + 1], __float_as_uint(fmaxf(c.y, 0.f)));
    }
    if (MODE & 4) {
        atomicAdd(&s_red[2 * lane],     c.x);
        atomicAdd(&s_red[2 * lane + 1], c.y);
        atomicAdd(&s_red[64 + 2 * lane],     c.x * c.x);
        atomicAdd(&s_red[64 + 2 * lane + 1], c.y * c.y);
        __syncthreads();
        if (threadIdx.x < 128)
            atomicAdd(&g_bn[128 * (l & 1) + threadIdx.x], s_red[threadIdx.x]);
    }
}

// ---------------- head ----------------
__global__ void k_out(const float* __restrict__ linW, const float* __restrict__ linb,
                      float* __restrict__ out) {
    int i = blockIdx.x * blockDim.x + threadIdx.x;
    if (i >= N_GRAPHS * 2) return;
    int g = i >> 1, cls = i & 1;
    float sacc = linb[cls];
    #pragma unroll 8
    for (int k = 0; k < 64; k++) sacc += g_pool[g * 64 + k] * linW[k * 2 + cls];
    out[i] = sacc;
}

// ---------------- orchestration ----------------
extern "C" void kernel_launch(void* const* d_in, const int* in_sizes, int n_in,
                              void* d_out, int out_size) {
    const float* x     = (const float*)d_in[0];
    const int*   ei    = (const int*)d_in[1];
    const int*   batch = (const int*)d_in[2];
    const float* attr  = (const float*)d_in[4];
    const float* Wlin1 = (const float*)d_in[5];
    const float* bias1 = (const float*)d_in[6];
    const float* m1W1  = (const float*)d_in[7];
    const float* m1b1  = (const float*)d_in[8];
    const float* m2W1  = (const float*)d_in[9];
    const float* m2b1  = (const float*)d_in[10];
    const float* hWlin = (const float*)d_in[11];
    const float* hbias = (const float*)d_in[12];
    const float* hm1W  = (const float*)d_in[13];
    const float* hm1b  = (const float*)d_in[14];
    const float* hm2W  = (const float*)d_in[15];
    const float* hm2b  = (const float*)d_in[16];
    const float* linW  = (const float*)d_in[17];
    const float* linb  = (const float*)d_in[18];
    (void)in_sizes; (void)n_in; (void)out_size;

    const int* src = ei;
    const int* dst = ei + N_EDGES;

    void* p_cnt;
    cudaGetSymbolAddress(&p_cnt, g_cnt);

    // CSR by dst
    cudaMemsetAsync(p_cnt, 0, N_NODES * sizeof(int));
    k_hist<<<(N_EDGES + 255) / 256, 256>>>(dst);
    k_scan1<<<NCHUNK, 1024>>>();
    k_scan2<<<1, 64>>>();
    k_scan3<<<(N_NODES + 255) / 256, 256>>>();
    k_scatter<<<(N_EDGES + 255) / 256, 256>>>(src, dst);

    // edge weights (all 13 layers, per CSR slot) + per-layer node norms (also zeroes pool)
    k_edge_mlp<<<(N_EDGES + 256 * EPT - 1) / (256 * EPT), 256>>>(
        attr, m1W1, m1b1, m2W1, m2b1, hm1W, hm1b, hm2W, hm2b);
    k_dis<<<(NL * N_NODES + 255) / 256, 256>>>();

    const int gemm_blocks = (N_NODES + 63) / 64;
    const int agg_blocks = N_NODES / 8;   // 6250, exact

    // layer 0: no BN; init S; stats for layer 1
    k_gemm<0><<<gemm_blocks, 256>>>(x, Wlin1, 0, 0);
    k_agg<5><<<agg_blocks, 256>>>(0, bias1, batch);

    // hidden layers 1..11
    for (int l = 1; l <= 11; l++) {
        k_gemm<1><<<gemm_blocks, 256>>>(nullptr, hWlin + (size_t)(l - 1) * C * C,
                                        128 * ((l - 1) & 1), 128 * (l & 1));
        if (l & 1)
            k_agg<4><<<agg_blocks, 256>>>(l, hbias + (size_t)(l - 1) * C, batch);
        else
            k_agg<6><<<agg_blocks, 256>>>(l, hbias + (size_t)(l - 1) * C, batch);
    }
    // layer 12: skip + relu + pool, no stats
    k_gemm<1><<<gemm_blocks, 256>>>(nullptr, hWlin + (size_t)11 * C * C, 128, 0);
    k_agg<10><<<agg_blocks, 256>>>(12, hbias + (size_t)11 * C, batch);

    k_out<<<(N_GRAPHS * 2 + 255) / 256, 256>>>(linW, linb, (float*)d_out);
}